// round 13
// baseline (speedup 1.0000x reference)
#include <cuda_runtime.h>
#include <math.h>
#include <stdint.h>

#define SS 256
#define BB 64
#define FF 512
#define HH 2048
#define VV 32000
#define RT (SS*BB)   // 16384 rows (s-major: r = s*64 + b)

// ------------------------- scratch (device globals; no allocs) -------------
__device__ float g_V[(size_t)RT*FF];   // gathered embeddings
__device__ float g_P[(size_t)RT*FF];   // vecs@see_top + bias; later reused as LN output Y
__device__ float g_C[(size_t)RT*FF];   // cont (state history)
__device__ float g_H[(size_t)RT*HH];   // hidden
__device__ float g_O[(size_t)RT*FF];   // MLP output
__device__ float g_se[RT];             // sum of exp(logits)
__device__ float g_tl[RT];             // target logit
__device__ float g_mask[RT];
__device__ int   g_in64, g_tg64;

#define INV_SQRT_F 0.044194173824159216f

// ------------------------- small helpers -----------------------------------
__device__ __forceinline__ unsigned long long pack2(float lo, float hi){
    unsigned long long r;
    asm("mov.b64 %0, {%1, %2};" : "=l"(r) : "f"(lo), "f"(hi));
    return r;
}
__device__ __forceinline__ void fma2(unsigned long long &acc, unsigned long long a, unsigned long long b){
    asm("fma.rn.f32x2 %0, %1, %2, %0;" : "+l"(acc) : "l"(a), "l"(b));
}
__device__ __forceinline__ float2 unpack2(unsigned long long v){
    float2 r;
    asm("mov.b64 {%0, %1}, %2;" : "=f"(r.x), "=f"(r.y) : "l"(v));
    return r;
}
__device__ __forceinline__ int load_idx(const void* p, int pos, int is64){
    if (is64) return (int)((const long long*)p)[pos];
    return ((const int*)p)[pos];
}

// ------------------------- kernel 0: init + dtype detect -------------------
__global__ void k_init(const int* inw, const int* tgw, float* out){
    __shared__ int f0, f1;
    int tid = threadIdx.x;
    if (tid == 0){ f0 = 1; f1 = 1; out[0] = 0.f; }
    __syncthreads();
    // int64 little-endian non-negative values < 2^31 => every odd 32-bit word is 0.
    for (int p = tid; p < RT; p += blockDim.x){
        if (p & 1){
            if (inw[p] != 0) f0 = 0;
            if (tgw[p] != 0) f1 = 0;
        }
    }
    __syncthreads();
    if (tid == 0){ g_in64 = f0; g_tg64 = f1; }
}

// ------------------------- kernel 1: embedding gather ----------------------
__global__ void k_gather(const void* __restrict__ inp, const float* __restrict__ emb){
    int r = blockIdx.x;
    int s = r >> 6, b = r & 63;
    int idx = load_idx(inp, b*SS + s, g_in64);
    int f = threadIdx.x * 4;
    float4 v = make_float4(0.f,0.f,0.f,0.f);
    if (idx != 0) v = *(const float4*)(emb + (size_t)idx*FF + f);   // padding_idx row -> 0
    *(float4*)(g_V + (size_t)r*FF + f) = v;
}

// ------------------------- generic tiled GEMM -------------------------------
// C[M,N] = A[M,K] * B   (A row-major, K contiguous)
// KMAJ=true : B is [N,K] with K contiguous  (C = A * B^T)
// KMAJ=false: B is [K,N] with N contiguous  (C = A * B)
// EPI: 0 = +bias ; 1 = relu(+bias) ; 2 = logits mode (scale, exp, row-sum -> atomicAdd g_se)
template<int EPI, bool KMAJ>
__global__ void __launch_bounds__(256) k_gemm(
        const float* __restrict__ A, const float* __restrict__ Bm,
        const float* __restrict__ bias, float* __restrict__ C,
        int M, int N, int K)
{
    const int BK = 16;
    __shared__ __align__(16) float As[BK][128];
    __shared__ __align__(16) float Bs[BK][128];

    int tid = threadIdx.x;
    int n0 = blockIdx.x * 128;
    int m0 = blockIdx.y * 128;
    int tx = tid & 15, ty = tid >> 4;

    int a_m = tid >> 2;            // 0..63
    int a_k = (tid & 3) << 2;      // 0,4,8,12
    int bn_k = tid >> 5;           // 0..7   (NN loader)
    int bn_n = (tid & 31) << 2;    // 0..124

    float4 ar[2], br[2];
    {
        const float* Ap = A + (size_t)(m0 + a_m)*K + a_k;
        ar[0] = *(const float4*)Ap;
        ar[1] = *(const float4*)(Ap + (size_t)64*K);
        if (KMAJ){
            const float* Bp = Bm + (size_t)(n0 + a_m)*K + a_k;
            br[0] = *(const float4*)Bp;
            br[1] = *(const float4*)(Bp + (size_t)64*K);
        } else {
            const float* Bp = Bm + (size_t)bn_k*N + n0 + bn_n;
            br[0] = *(const float4*)Bp;
            br[1] = *(const float4*)(Bp + (size_t)8*N);
        }
    }

    unsigned long long acc[8][4];
    #pragma unroll
    for (int i=0;i<8;i++)
        #pragma unroll
        for (int j=0;j<4;j++) acc[i][j] = 0ull;

    for (int kt = 0; kt < K; kt += BK){
        As[a_k+0][a_m]    = ar[0].x; As[a_k+1][a_m]    = ar[0].y;
        As[a_k+2][a_m]    = ar[0].z; As[a_k+3][a_m]    = ar[0].w;
        As[a_k+0][a_m+64] = ar[1].x; As[a_k+1][a_m+64] = ar[1].y;
        As[a_k+2][a_m+64] = ar[1].z; As[a_k+3][a_m+64] = ar[1].w;
        if (KMAJ){
            Bs[a_k+0][a_m]    = br[0].x; Bs[a_k+1][a_m]    = br[0].y;
            Bs[a_k+2][a_m]    = br[0].z; Bs[a_k+3][a_m]    = br[0].w;
            Bs[a_k+0][a_m+64] = br[1].x; Bs[a_k+1][a_m+64] = br[1].y;
            Bs[a_k+2][a_m+64] = br[1].z; Bs[a_k+3][a_m+64] = br[1].w;
        } else {
            *(float4*)&Bs[bn_k  ][bn_n] = br[0];
            *(float4*)&Bs[bn_k+8][bn_n] = br[1];
        }
        __syncthreads();

        if (kt + BK < K){   // software pipeline: prefetch next slab into regs
            const float* Ap = A + (size_t)(m0 + a_m)*K + (kt + BK) + a_k;
            ar[0] = *(const float4*)Ap;
            ar[1] = *(const float4*)(Ap + (size_t)64*K);
            if (KMAJ){
                const float* Bp = Bm + (size_t)(n0 + a_m)*K + (kt + BK) + a_k;
                br[0] = *(const float4*)Bp;
                br[1] = *(const float4*)(Bp + (size_t)64*K);
            } else {
                const float* Bp = Bm + (size_t)(kt + BK + bn_k)*N + n0 + bn_n;
                br[0] = *(const float4*)Bp;
                br[1] = *(const float4*)(Bp + (size_t)8*N);
            }
        }

        #pragma unroll
        for (int k = 0; k < BK; k++){
            float4 a0 = *(const float4*)&As[k][ty*8];
            float4 a1 = *(const float4*)&As[k][ty*8+4];
            float4 b0 = *(const float4*)&Bs[k][tx*8];
            float4 b1 = *(const float4*)&Bs[k][tx*8+4];
            unsigned long long b2[4] = {
                pack2(b0.x,b0.y), pack2(b0.z,b0.w),
                pack2(b1.x,b1.y), pack2(b1.z,b1.w) };
            float a[8] = {a0.x,a0.y,a0.z,a0.w,a1.x,a1.y,a1.z,a1.w};
            #pragma unroll
            for (int i=0;i<8;i++){
                unsigned long long ad = pack2(a[i], a[i]);
                #pragma unroll
                for (int j=0;j<4;j++) fma2(acc[i][j], ad, b2[j]);
            }
        }
        __syncthreads();
    }

    if (EPI == 2){
        // logits: e = exp(acc * 1/sqrt(F)); column 0 excluded (emb_m row 0 == 0,
        // its exp(0)=1 is pre-added in g_se init); per-row partial sums via atomics.
        #pragma unroll
        for (int i=0;i<8;i++){
            int m = m0 + ty*8 + i;
            float rs = 0.f;
            #pragma unroll
            for (int j=0;j<4;j++){
                float2 t = unpack2(acc[i][j]);
                int n = n0 + tx*8 + 2*j;
                float e0 = (n == 0) ? 0.f : __expf(t.x * INV_SQRT_F);
                float e1 = __expf(t.y * INV_SQRT_F);
                rs += e0 + e1;
            }
            rs += __shfl_down_sync(0xffffffffu, rs, 8, 16);
            rs += __shfl_down_sync(0xffffffffu, rs, 4, 16);
            rs += __shfl_down_sync(0xffffffffu, rs, 2, 16);
            rs += __shfl_down_sync(0xffffffffu, rs, 1, 16);
            if (tx == 0) atomicAdd(&g_se[m], rs);
        }
    } else {
        float bv[8];
        #pragma unroll
        for (int j=0;j<8;j++) bv[j] = bias[n0 + tx*8 + j];
        #pragma unroll
        for (int i=0;i<8;i++){
            int m = m0 + ty*8 + i;
            float o[8];
            #pragma unroll
            for (int j=0;j<4;j++){
                float2 t = unpack2(acc[i][j]);
                o[2*j]   = t.x + bv[2*j];
                o[2*j+1] = t.y + bv[2*j+1];
            }
            if (EPI == 1){
                #pragma unroll
                for (int j=0;j<8;j++) o[j] = fmaxf(o[j], 0.f);
            }
            float* cp = C + (size_t)m*N + n0 + tx*8;
            *(float4*)cp       = make_float4(o[0],o[1],o[2],o[3]);
            *(float4*)(cp + 4) = make_float4(o[4],o[5],o[6],o[7]);
        }
    }
}

// ------------------------- recurrence: one step -----------------------------
// gate = sigmoid(P[s] + state @ see[F:2F, :]);  C[s] = state*gate + vecs*(1-gate)
__global__ void __launch_bounds__(256) k_recurr(const float* __restrict__ see, int s){
    __shared__ float Ssm[64][129];  // state chunk [b][k], padded
    __shared__ float Bsm[128][8];   // see_bot chunk [k][j]
    int tid = threadIdx.x;
    int j0 = blockIdx.x * 8;
    int b  = tid & 63;
    int jg = tid >> 6;              // 0..3

    float acc0 = 0.f, acc1 = 0.f;
    if (s > 0){
        const float* st = g_C + (size_t)(s-1)*BB*FF;
        for (int kc = 0; kc < FF; kc += 128){
            for (int t = tid*4; t < 64*128; t += 1024){
                int br = t >> 7, k = t & 127;
                float4 v = *(const float4*)(st + (size_t)br*FF + kc + k);
                Ssm[br][k] = v.x; Ssm[br][k+1] = v.y; Ssm[br][k+2] = v.z; Ssm[br][k+3] = v.w;
            }
            {
                int k = tid >> 1, jj = (tid & 1) * 4;
                float4 v = *(const float4*)(see + (size_t)(FF + kc + k)*FF + j0 + jj);
                Bsm[k][jj] = v.x; Bsm[k][jj+1] = v.y; Bsm[k][jj+2] = v.z; Bsm[k][jj+3] = v.w;
            }
            __syncthreads();
            #pragma unroll 8
            for (int k = 0; k < 128; k++){
                float sv = Ssm[b][k];
                acc0 = fmaf(sv, Bsm[k][jg],   acc0);
                acc1 = fmaf(sv, Bsm[k][jg+4], acc1);
            }
            __syncthreads();
        }
    }
    size_t ro = ((size_t)s*BB + b)*FF;
    {
        int j = j0 + jg;
        float g1 = 1.f / (1.f + expf(-(g_P[ro + j] + acc0)));
        float sv = (s > 0) ? g_C[ro - (size_t)BB*FF + j] : 0.f;
        float vv = g_V[ro + j];
        g_C[ro + j] = sv*g1 + vv*(1.f - g1);
    }
    {
        int j = j0 + jg + 4;
        float g1 = 1.f / (1.f + expf(-(g_P[ro + j] + acc1)));
        float sv = (s > 0) ? g_C[ro - (size_t)BB*FF + j] : 0.f;
        float vv = g_V[ro + j];
        g_C[ro + j] = sv*g1 + vv*(1.f - g1);
    }
}

// ------------------------- layernorm (writes into g_P) ----------------------
__global__ void __launch_bounds__(128) k_ln(const float* __restrict__ gam, const float* __restrict__ bet){
    int r = blockIdx.x;
    const float* x = g_C + (size_t)r*FF;
    float*       y = g_P + (size_t)r*FF;
    int tid = threadIdx.x;
    float4 v = *(const float4*)(x + tid*4);
    float s = v.x + v.y + v.z + v.w;
    float q = v.x*v.x + v.y*v.y + v.z*v.z + v.w*v.w;
    #pragma unroll
    for (int off = 16; off; off >>= 1){
        s += __shfl_down_sync(0xffffffffu, s, off);
        q += __shfl_down_sync(0xffffffffu, q, off);
    }
    __shared__ float ss[4], qq[4];
    int w = tid >> 5, lane = tid & 31;
    if (lane == 0){ ss[w] = s; qq[w] = q; }
    __syncthreads();
    float S = ss[0]+ss[1]+ss[2]+ss[3];
    float Q = qq[0]+qq[1]+qq[2]+qq[3];
    float mu  = S * (1.f/FF);
    float var = Q * (1.f/FF) - mu*mu;
    float rstd = rsqrtf(var + 1e-5f);
    float4 gg = *(const float4*)(gam + tid*4);
    float4 bb = *(const float4*)(bet + tid*4);
    float4 o;
    o.x = (v.x - mu)*rstd*gg.x + bb.x;
    o.y = (v.y - mu)*rstd*gg.y + bb.y;
    o.z = (v.z - mu)*rstd*gg.z + bb.z;
    o.w = (v.w - mu)*rstd*gg.w + bb.w;
    *(float4*)(y + tid*4) = o;
}

// ------------------------- target logit + sumexp init -----------------------
__global__ void __launch_bounds__(256) k_tgt(const void* __restrict__ tg, const float* __restrict__ emb){
    int tid = threadIdx.x, lane = tid & 31, w = tid >> 5;
    int r = blockIdx.x * 8 + w;
    int s = r >> 6, b = r & 63;
    int t = load_idx(tg, b*SS + s, g_tg64);
    float dot = 0.f;
    if (t != 0){
        const float4* o = (const float4*)(g_O + (size_t)r*FF);
        const float4* e = (const float4*)(emb + (size_t)t*FF);
        #pragma unroll
        for (int it = 0; it < 4; it++){
            float4 ov = o[lane + 32*it];
            float4 ev = e[lane + 32*it];
            dot += ov.x*ev.x + ov.y*ev.y + ov.z*ev.z + ov.w*ev.w;
        }
    }
    #pragma unroll
    for (int off = 16; off; off >>= 1) dot += __shfl_down_sync(0xffffffffu, dot, off);
    if (lane == 0){
        g_tl[r]   = dot * INV_SQRT_F;
        g_mask[r] = (t != 0) ? 1.f : 0.f;
        g_se[r]   = 1.f;   // exp(logit[v=0]) = exp(0): emb_m row 0 is zero
    }
}

// ------------------------- per-step loss + global mean -----------------------
__global__ void __launch_bounds__(64) k_loss(float* __restrict__ out){
    int s = blockIdx.x, b = threadIdx.x;
    int r = s*BB + b;
    float m   = g_mask[r];
    float nll = (logf(g_se[r]) - g_tl[r]) * m;
    float nn = nll, mm = m;
    #pragma unroll
    for (int off = 16; off; off >>= 1){
        nn += __shfl_down_sync(0xffffffffu, nn, off);
        mm += __shfl_down_sync(0xffffffffu, mm, off);
    }
    __shared__ float sn[2], sm[2];
    if ((b & 31) == 0){ sn[b>>5] = nn; sm[b>>5] = mm; }
    __syncthreads();
    if (b == 0){
        float N_ = sn[0] + sn[1], M_ = sm[0] + sm[1];
        atomicAdd(out, (N_ / fmaxf(M_, 1.f)) * (1.f/SS));
    }
}

// ------------------------- launch -------------------------------------------
extern "C" void kernel_launch(void* const* d_in, const int* in_sizes, int n_in,
                              void* d_out, int out_size){
    const void*  inp   = d_in[0];
    const void*  tgt   = d_in[1];
    const float* see   = (const float*)d_in[2];
    const float* bias  = (const float*)d_in[3];
    const float* W_in  = (const float*)d_in[4];
    const float* b_in  = (const float*)d_in[5];
    const float* W_out = (const float*)d_in[6];
    const float* b_out = (const float*)d_in[7];
    const float* ln_g  = (const float*)d_in[8];
    const float* ln_b  = (const float*)d_in[9];
    const float* emb   = (const float*)d_in[10];
    float* out = (float*)d_out;

    void *pV, *pP, *pC, *pH, *pO;
    cudaGetSymbolAddress(&pV, g_V);
    cudaGetSymbolAddress(&pP, g_P);
    cudaGetSymbolAddress(&pC, g_C);
    cudaGetSymbolAddress(&pH, g_H);
    cudaGetSymbolAddress(&pO, g_O);

    k_init<<<1, 256>>>((const int*)inp, (const int*)tgt, out);
    k_gather<<<RT, 128>>>(inp, emb);

    // P = Vecs @ see_top + bias      (B is [K,N] n-contiguous)
    k_gemm<0,false><<<dim3(FF/128, RT/128), 256>>>((const float*)pV, see, bias, (float*)pP, RT, FF, FF);

    for (int s = 0; s < SS; s++)
        k_recurr<<<FF/8, 256>>>(see, s);

    k_ln<<<RT, 128>>>(ln_g, ln_b);    // Y -> g_P (reuse)

    // H = relu(Y @ W_in^T + b_in)
    k_gemm<1,true><<<dim3(HH/128, RT/128), 256>>>((const float*)pP, W_in, b_in, (float*)pH, RT, HH, FF);
    // O = H @ W_out^T + b_out
    k_gemm<0,true><<<dim3(FF/128, RT/128), 256>>>((const float*)pH, W_out, b_out, (float*)pO, RT, FF, HH);

    k_tgt<<<RT/8, 256>>>(tgt, emb);

    // logits + streamed sum-exp (no logits buffer)
    k_gemm<2,true><<<dim3(VV/128, RT/128), 256>>>((const float*)pO, emb, nullptr, nullptr, RT, VV, FF);

    k_loss<<<SS, 64>>>(out);
}

// round 14
// speedup vs baseline: 1.0014x; 1.0014x over previous
#include <cuda_runtime.h>
#include <math.h>
#include <stdint.h>

#define SS 256
#define BB 64
#define FF 512
#define HH 2048
#define VV 32000
#define RT (SS*BB)   // 16384 rows (s-major: r = s*64 + b)

// ------------------------- scratch (device globals; no allocs) -------------
__device__ float g_V[(size_t)RT*FF];   // gathered embeddings
__device__ float g_P[(size_t)RT*FF];   // vecs@see_top + bias; later reused as LN output Y
__device__ float g_C[(size_t)RT*FF];   // cont (state history)
__device__ float g_H[(size_t)RT*HH];   // hidden
__device__ float g_O[(size_t)RT*FF];   // MLP output
__device__ float g_se[RT];             // sum of exp(logits)
__device__ float g_tl[RT];             // target logit
__device__ float g_mask[RT];
__device__ int   g_in64, g_tg64;

#define INV_SQRT_F 0.044194173824159216f

// ------------------------- small helpers -----------------------------------
__device__ __forceinline__ unsigned long long pack2(float lo, float hi){
    unsigned long long r;
    asm("mov.b64 %0, {%1, %2};" : "=l"(r) : "f"(lo), "f"(hi));
    return r;
}
__device__ __forceinline__ void fma2(unsigned long long &acc, unsigned long long a, unsigned long long b){
    asm("fma.rn.f32x2 %0, %1, %2, %0;" : "+l"(acc) : "l"(a), "l"(b));
}
__device__ __forceinline__ float2 unpack2(unsigned long long v){
    float2 r;
    asm("mov.b64 {%0, %1}, %2;" : "=f"(r.x), "=f"(r.y) : "l"(v));
    return r;
}
__device__ __forceinline__ int load_idx(const void* p, int pos, int is64){
    if (is64) return (int)((const long long*)p)[pos];
    return ((const int*)p)[pos];
}

// ------------------------- kernel 0: init + dtype detect -------------------
__global__ void k_init(const int* inw, const int* tgw, float* out){
    __shared__ int f0, f1;
    int tid = threadIdx.x;
    if (tid == 0){ f0 = 1; f1 = 1; out[0] = 0.f; }
    __syncthreads();
    // int64 little-endian non-negative values < 2^31 => every odd 32-bit word is 0.
    for (int p = tid; p < RT; p += blockDim.x){
        if (p & 1){
            if (inw[p] != 0) f0 = 0;
            if (tgw[p] != 0) f1 = 0;
        }
    }
    __syncthreads();
    if (tid == 0){ g_in64 = f0; g_tg64 = f1; }
}

// ------------------------- kernel 1: embedding gather ----------------------
__global__ void k_gather(const void* __restrict__ inp, const float* __restrict__ emb){
    int r = blockIdx.x;
    int s = r >> 6, b = r & 63;
    int idx = load_idx(inp, b*SS + s, g_in64);
    int f = threadIdx.x * 4;
    float4 v = make_float4(0.f,0.f,0.f,0.f);
    if (idx != 0) v = *(const float4*)(emb + (size_t)idx*FF + f);   // padding_idx row -> 0
    *(float4*)(g_V + (size_t)r*FF + f) = v;
}

// ------------------------- generic tiled GEMM -------------------------------
// C[M,N] = A[M,K] * B   (A row-major, K contiguous)
// KMAJ=true : B is [N,K] with K contiguous  (C = A * B^T)
// KMAJ=false: B is [K,N] with N contiguous  (C = A * B)
// EPI: 0 = +bias ; 1 = relu(+bias) ; 2 = logits mode (scale, exp, row-sum -> atomicAdd g_se)
template<int EPI, bool KMAJ>
__global__ void __launch_bounds__(256) k_gemm(
        const float* __restrict__ A, const float* __restrict__ Bm,
        const float* __restrict__ bias, float* __restrict__ C,
        int M, int N, int K)
{
    const int BK = 16;
    __shared__ __align__(16) float As[BK][128];
    __shared__ __align__(16) float Bs[BK][128];

    int tid = threadIdx.x;
    int n0 = blockIdx.x * 128;
    int m0 = blockIdx.y * 128;
    int tx = tid & 15, ty = tid >> 4;

    int a_m = tid >> 2;            // 0..63
    int a_k = (tid & 3) << 2;      // 0,4,8,12
    int bn_k = tid >> 5;           // 0..7   (NN loader)
    int bn_n = (tid & 31) << 2;    // 0..124

    float4 ar[2], br[2];
    {
        const float* Ap = A + (size_t)(m0 + a_m)*K + a_k;
        ar[0] = *(const float4*)Ap;
        ar[1] = *(const float4*)(Ap + (size_t)64*K);
        if (KMAJ){
            const float* Bp = Bm + (size_t)(n0 + a_m)*K + a_k;
            br[0] = *(const float4*)Bp;
            br[1] = *(const float4*)(Bp + (size_t)64*K);
        } else {
            const float* Bp = Bm + (size_t)bn_k*N + n0 + bn_n;
            br[0] = *(const float4*)Bp;
            br[1] = *(const float4*)(Bp + (size_t)8*N);
        }
    }

    unsigned long long acc[8][4];
    #pragma unroll
    for (int i=0;i<8;i++)
        #pragma unroll
        for (int j=0;j<4;j++) acc[i][j] = 0ull;

    for (int kt = 0; kt < K; kt += BK){
        As[a_k+0][a_m]    = ar[0].x; As[a_k+1][a_m]    = ar[0].y;
        As[a_k+2][a_m]    = ar[0].z; As[a_k+3][a_m]    = ar[0].w;
        As[a_k+0][a_m+64] = ar[1].x; As[a_k+1][a_m+64] = ar[1].y;
        As[a_k+2][a_m+64] = ar[1].z; As[a_k+3][a_m+64] = ar[1].w;
        if (KMAJ){
            Bs[a_k+0][a_m]    = br[0].x; Bs[a_k+1][a_m]    = br[0].y;
            Bs[a_k+2][a_m]    = br[0].z; Bs[a_k+3][a_m]    = br[0].w;
            Bs[a_k+0][a_m+64] = br[1].x; Bs[a_k+1][a_m+64] = br[1].y;
            Bs[a_k+2][a_m+64] = br[1].z; Bs[a_k+3][a_m+64] = br[1].w;
        } else {
            *(float4*)&Bs[bn_k  ][bn_n] = br[0];
            *(float4*)&Bs[bn_k+8][bn_n] = br[1];
        }
        __syncthreads();

        if (kt + BK < K){   // software pipeline: prefetch next slab into regs
            const float* Ap = A + (size_t)(m0 + a_m)*K + (kt + BK) + a_k;
            ar[0] = *(const float4*)Ap;
            ar[1] = *(const float4*)(Ap + (size_t)64*K);
            if (KMAJ){
                const float* Bp = Bm + (size_t)(n0 + a_m)*K + (kt + BK) + a_k;
                br[0] = *(const float4*)Bp;
                br[1] = *(const float4*)(Bp + (size_t)64*K);
            } else {
                const float* Bp = Bm + (size_t)(kt + BK + bn_k)*N + n0 + bn_n;
                br[0] = *(const float4*)Bp;
                br[1] = *(const float4*)(Bp + (size_t)8*N);
            }
        }

        #pragma unroll
        for (int k = 0; k < BK; k++){
            float4 a0 = *(const float4*)&As[k][ty*8];
            float4 a1 = *(const float4*)&As[k][ty*8+4];
            float4 b0 = *(const float4*)&Bs[k][tx*8];
            float4 b1 = *(const float4*)&Bs[k][tx*8+4];
            unsigned long long b2[4] = {
                pack2(b0.x,b0.y), pack2(b0.z,b0.w),
                pack2(b1.x,b1.y), pack2(b1.z,b1.w) };
            float a[8] = {a0.x,a0.y,a0.z,a0.w,a1.x,a1.y,a1.z,a1.w};
            #pragma unroll
            for (int i=0;i<8;i++){
                unsigned long long ad = pack2(a[i], a[i]);
                #pragma unroll
                for (int j=0;j<4;j++) fma2(acc[i][j], ad, b2[j]);
            }
        }
        __syncthreads();
    }

    if (EPI == 2){
        // logits: e = exp(acc * 1/sqrt(F)); column 0 excluded (emb_m row 0 == 0,
        // its exp(0)=1 is pre-added in g_se init); per-row partial sums via atomics.
        #pragma unroll
        for (int i=0;i<8;i++){
            int m = m0 + ty*8 + i;
            float rs = 0.f;
            #pragma unroll
            for (int j=0;j<4;j++){
                float2 t = unpack2(acc[i][j]);
                int n = n0 + tx*8 + 2*j;
                float e0 = (n == 0) ? 0.f : __expf(t.x * INV_SQRT_F);
                float e1 = __expf(t.y * INV_SQRT_F);
                rs += e0 + e1;
            }
            rs += __shfl_down_sync(0xffffffffu, rs, 8, 16);
            rs += __shfl_down_sync(0xffffffffu, rs, 4, 16);
            rs += __shfl_down_sync(0xffffffffu, rs, 2, 16);
            rs += __shfl_down_sync(0xffffffffu, rs, 1, 16);
            if (tx == 0) atomicAdd(&g_se[m], rs);
        }
    } else {
        float bv[8];
        #pragma unroll
        for (int j=0;j<8;j++) bv[j] = bias[n0 + tx*8 + j];
        #pragma unroll
        for (int i=0;i<8;i++){
            int m = m0 + ty*8 + i;
            float o[8];
            #pragma unroll
            for (int j=0;j<4;j++){
                float2 t = unpack2(acc[i][j]);
                o[2*j]   = t.x + bv[2*j];
                o[2*j+1] = t.y + bv[2*j+1];
            }
            if (EPI == 1){
                #pragma unroll
                for (int j=0;j<8;j++) o[j] = fmaxf(o[j], 0.f);
            }
            float* cp = C + (size_t)m*N + n0 + tx*8;
            *(float4*)cp       = make_float4(o[0],o[1],o[2],o[3]);
            *(float4*)(cp + 4) = make_float4(o[4],o[5],o[6],o[7]);
        }
    }
}

// ------------------------- recurrence: one step -----------------------------
// gate = sigmoid(P[s] + state @ see[F:2F, :]);  C[s] = state*gate + vecs*(1-gate)
__global__ void __launch_bounds__(256) k_recurr(const float* __restrict__ see, int s){
    __shared__ float Ssm[64][129];  // state chunk [b][k], padded
    __shared__ float Bsm[128][8];   // see_bot chunk [k][j]
    int tid = threadIdx.x;
    int j0 = blockIdx.x * 8;
    int b  = tid & 63;
    int jg = tid >> 6;              // 0..3

    float acc0 = 0.f, acc1 = 0.f;
    if (s > 0){
        const float* st = g_C + (size_t)(s-1)*BB*FF;
        for (int kc = 0; kc < FF; kc += 128){
            for (int t = tid*4; t < 64*128; t += 1024){
                int br = t >> 7, k = t & 127;
                float4 v = *(const float4*)(st + (size_t)br*FF + kc + k);
                Ssm[br][k] = v.x; Ssm[br][k+1] = v.y; Ssm[br][k+2] = v.z; Ssm[br][k+3] = v.w;
            }
            {
                int k = tid >> 1, jj = (tid & 1) * 4;
                float4 v = *(const float4*)(see + (size_t)(FF + kc + k)*FF + j0 + jj);
                Bsm[k][jj] = v.x; Bsm[k][jj+1] = v.y; Bsm[k][jj+2] = v.z; Bsm[k][jj+3] = v.w;
            }
            __syncthreads();
            #pragma unroll 8
            for (int k = 0; k < 128; k++){
                float sv = Ssm[b][k];
                acc0 = fmaf(sv, Bsm[k][jg],   acc0);
                acc1 = fmaf(sv, Bsm[k][jg+4], acc1);
            }
            __syncthreads();
        }
    }
    size_t ro = ((size_t)s*BB + b)*FF;
    {
        int j = j0 + jg;
        float g1 = 1.f / (1.f + expf(-(g_P[ro + j] + acc0)));
        float sv = (s > 0) ? g_C[ro - (size_t)BB*FF + j] : 0.f;
        float vv = g_V[ro + j];
        g_C[ro + j] = sv*g1 + vv*(1.f - g1);
    }
    {
        int j = j0 + jg + 4;
        float g1 = 1.f / (1.f + expf(-(g_P[ro + j] + acc1)));
        float sv = (s > 0) ? g_C[ro - (size_t)BB*FF + j] : 0.f;
        float vv = g_V[ro + j];
        g_C[ro + j] = sv*g1 + vv*(1.f - g1);
    }
}

// ------------------------- layernorm (writes into g_P) ----------------------
__global__ void __launch_bounds__(128) k_ln(const float* __restrict__ gam, const float* __restrict__ bet){
    int r = blockIdx.x;
    const float* x = g_C + (size_t)r*FF;
    float*       y = g_P + (size_t)r*FF;
    int tid = threadIdx.x;
    float4 v = *(const float4*)(x + tid*4);
    float s = v.x + v.y + v.z + v.w;
    float q = v.x*v.x + v.y*v.y + v.z*v.z + v.w*v.w;
    #pragma unroll
    for (int off = 16; off; off >>= 1){
        s += __shfl_down_sync(0xffffffffu, s, off);
        q += __shfl_down_sync(0xffffffffu, q, off);
    }
    __shared__ float ss[4], qq[4];
    int w = tid >> 5, lane = tid & 31;
    if (lane == 0){ ss[w] = s; qq[w] = q; }
    __syncthreads();
    float S = ss[0]+ss[1]+ss[2]+ss[3];
    float Q = qq[0]+qq[1]+qq[2]+qq[3];
    float mu  = S * (1.f/FF);
    float var = Q * (1.f/FF) - mu*mu;
    float rstd = rsqrtf(var + 1e-5f);
    float4 gg = *(const float4*)(gam + tid*4);
    float4 bb = *(const float4*)(bet + tid*4);
    float4 o;
    o.x = (v.x - mu)*rstd*gg.x + bb.x;
    o.y = (v.y - mu)*rstd*gg.y + bb.y;
    o.z = (v.z - mu)*rstd*gg.z + bb.z;
    o.w = (v.w - mu)*rstd*gg.w + bb.w;
    *(float4*)(y + tid*4) = o;
}

// ------------------------- target logit + sumexp init -----------------------
__global__ void __launch_bounds__(256) k_tgt(const void* __restrict__ tg, const float* __restrict__ emb){
    int tid = threadIdx.x, lane = tid & 31, w = tid >> 5;
    int r = blockIdx.x * 8 + w;
    int s = r >> 6, b = r & 63;
    int t = load_idx(tg, b*SS + s, g_tg64);
    float dot = 0.f;
    if (t != 0){
        const float4* o = (const float4*)(g_O + (size_t)r*FF);
        const float4* e = (const float4*)(emb + (size_t)t*FF);
        #pragma unroll
        for (int it = 0; it < 4; it++){
            float4 ov = o[lane + 32*it];
            float4 ev = e[lane + 32*it];
            dot += ov.x*ev.x + ov.y*ev.y + ov.z*ev.z + ov.w*ev.w;
        }
    }
    #pragma unroll
    for (int off = 16; off; off >>= 1) dot += __shfl_down_sync(0xffffffffu, dot, off);
    if (lane == 0){
        g_tl[r]   = dot * INV_SQRT_F;
        g_mask[r] = (t != 0) ? 1.f : 0.f;
        g_se[r]   = 1.f;   // exp(logit[v=0]) = exp(0): emb_m row 0 is zero
    }
}

// ------------------------- per-step loss + global mean -----------------------
__global__ void __launch_bounds__(64) k_loss(float* __restrict__ out){
    int s = blockIdx.x, b = threadIdx.x;
    int r = s*BB + b;
    float m   = g_mask[r];
    float nll = (logf(g_se[r]) - g_tl[r]) * m;
    float nn = nll, mm = m;
    #pragma unroll
    for (int off = 16; off; off >>= 1){
        nn += __shfl_down_sync(0xffffffffu, nn, off);
        mm += __shfl_down_sync(0xffffffffu, mm, off);
    }
    __shared__ float sn[2], sm[2];
    if ((b & 31) == 0){ sn[b>>5] = nn; sm[b>>5] = mm; }
    __syncthreads();
    if (b == 0){
        float N_ = sn[0] + sn[1], M_ = sm[0] + sm[1];
        atomicAdd(out, (N_ / fmaxf(M_, 1.f)) * (1.f/SS));
    }
}

// ------------------------- launch -------------------------------------------
extern "C" void kernel_launch(void* const* d_in, const int* in_sizes, int n_in,
                              void* d_out, int out_size){
    const void*  inp   = d_in[0];
    const void*  tgt   = d_in[1];
    const float* see   = (const float*)d_in[2];
    const float* bias  = (const float*)d_in[3];
    const float* W_in  = (const float*)d_in[4];
    const float* b_in  = (const float*)d_in[5];
    const float* W_out = (const float*)d_in[6];
    const float* b_out = (const float*)d_in[7];
    const float* ln_g  = (const float*)d_in[8];
    const float* ln_b  = (const float*)d_in[9];
    const float* emb   = (const float*)d_in[10];
    float* out = (float*)d_out;

    void *pV, *pP, *pC, *pH, *pO;
    cudaGetSymbolAddress(&pV, g_V);
    cudaGetSymbolAddress(&pP, g_P);
    cudaGetSymbolAddress(&pC, g_C);
    cudaGetSymbolAddress(&pH, g_H);
    cudaGetSymbolAddress(&pO, g_O);

    k_init<<<1, 256>>>((const int*)inp, (const int*)tgt, out);
    k_gather<<<RT, 128>>>(inp, emb);

    // P = Vecs @ see_top + bias      (B is [K,N] n-contiguous)
    k_gemm<0,false><<<dim3(FF/128, RT/128), 256>>>((const float*)pV, see, bias, (float*)pP, RT, FF, FF);

    for (int s = 0; s < SS; s++)
        k_recurr<<<FF/8, 256>>>(see, s);

    k_ln<<<RT, 128>>>(ln_g, ln_b);    // Y -> g_P (reuse)

    // H = relu(Y @ W_in^T + b_in)
    k_gemm<1,true><<<dim3(HH/128, RT/128), 256>>>((const float*)pP, W_in, b_in, (float*)pH, RT, HH, FF);
    // O = H @ W_out^T + b_out
    k_gemm<0,true><<<dim3(FF/128, RT/128), 256>>>((const float*)pH, W_out, b_out, (float*)pO, RT, FF, HH);

    k_tgt<<<RT/8, 256>>>(tgt, emb);

    // logits + streamed sum-exp (no logits buffer)
    k_gemm<2,true><<<dim3(VV/128, RT/128), 256>>>((const float*)pO, emb, nullptr, nullptr, RT, VV, FF);

    k_loss<<<SS, 64>>>(out);
}

// round 16
// speedup vs baseline: 1.9547x; 1.9519x over previous
#include <cuda_runtime.h>
#include <cuda_bf16.h>
#include <math.h>
#include <stdint.h>

#define SS 256
#define BB 64
#define FF 512
#define HH 2048
#define VV 32000
#define RT (SS*BB)   // 16384 rows (s-major: r = s*64 + b)

// ------------------------- scratch (device globals; no allocs) -------------
__device__ float g_V[(size_t)RT*FF];   // gathered embeddings
__device__ float g_P[(size_t)RT*FF];   // vecs@see_top + bias; later reused as LN output Y
__device__ float g_C[(size_t)RT*FF];   // cont (state history)
__device__ float g_H[(size_t)RT*HH];   // hidden
__device__ float g_O[(size_t)RT*FF];   // MLP output
__device__ __nv_bfloat16 g_embh[(size_t)VV*FF];  // bf16 emb (row 0 zeroed)
__device__ __nv_bfloat16 g_Oh[(size_t)RT*FF];    // bf16 O
__device__ float g_se[RT];             // sum of exp(logits)
__device__ float g_tl[RT];             // target logit
__device__ float g_mask[RT];
__device__ int   g_in64, g_tg64;

#define INV_SQRT_F 0.044194173824159216f

// ------------------------- small helpers -----------------------------------
__device__ __forceinline__ unsigned long long pack2(float lo, float hi){
    unsigned long long r;
    asm("mov.b64 %0, {%1, %2};" : "=l"(r) : "f"(lo), "f"(hi));
    return r;
}
__device__ __forceinline__ void fma2(unsigned long long &acc, unsigned long long a, unsigned long long b){
    asm("fma.rn.f32x2 %0, %1, %2, %0;" : "+l"(acc) : "l"(a), "l"(b));
}
__device__ __forceinline__ float2 unpack2(unsigned long long v){
    float2 r;
    asm("mov.b64 {%0, %1}, %2;" : "=f"(r.x), "=f"(r.y) : "l"(v));
    return r;
}
__device__ __forceinline__ int load_idx(const void* p, int pos, int is64){
    if (is64) return (int)((const long long*)p)[pos];
    return ((const int*)p)[pos];
}
__device__ __forceinline__ void mma_bf16(float* c, const uint32_t* a, const uint32_t* b){
    asm volatile("mma.sync.aligned.m16n8k16.row.col.f32.bf16.bf16.f32 "
        "{%0,%1,%2,%3}, {%4,%5,%6,%7}, {%8,%9}, {%0,%1,%2,%3};"
        : "+f"(c[0]), "+f"(c[1]), "+f"(c[2]), "+f"(c[3])
        : "r"(a[0]), "r"(a[1]), "r"(a[2]), "r"(a[3]), "r"(b[0]), "r"(b[1]));
}

// ------------------------- kernel 0: init + dtype detect -------------------
__global__ void k_init(const int* inw, const int* tgw, float* out){
    __shared__ int f0, f1;
    int tid = threadIdx.x;
    if (tid == 0){ f0 = 1; f1 = 1; out[0] = 0.f; }
    __syncthreads();
    // int64 little-endian non-negative values < 2^31 => every odd 32-bit word is 0.
    for (int p = tid; p < RT; p += blockDim.x){
        if (p & 1){
            if (inw[p] != 0) f0 = 0;
            if (tgw[p] != 0) f1 = 0;
        }
    }
    __syncthreads();
    if (tid == 0){ g_in64 = f0; g_tg64 = f1; }
}

// ------------------------- bf16 conversions ---------------------------------
__global__ void k_cvt_emb(const float* __restrict__ emb){
    size_t i = ((size_t)blockIdx.x*256 + threadIdx.x)*4;
    float4 v = *(const float4*)(emb + i);
    if (i < FF) v = make_float4(0.f,0.f,0.f,0.f);   // padding row 0 -> emb_m
    __nv_bfloat162 h0 = __float22bfloat162_rn(make_float2(v.x, v.y));
    __nv_bfloat162 h1 = __float22bfloat162_rn(make_float2(v.z, v.w));
    uint2 o = make_uint2(*(unsigned*)&h0, *(unsigned*)&h1);
    *(uint2*)(g_embh + i) = o;
}
__global__ void k_cvt_O(){
    size_t i = ((size_t)blockIdx.x*256 + threadIdx.x)*4;
    float4 v = *(const float4*)(g_O + i);
    __nv_bfloat162 h0 = __float22bfloat162_rn(make_float2(v.x, v.y));
    __nv_bfloat162 h1 = __float22bfloat162_rn(make_float2(v.z, v.w));
    uint2 o = make_uint2(*(unsigned*)&h0, *(unsigned*)&h1);
    *(uint2*)(g_Oh + i) = o;
}

// ------------------------- kernel 1: embedding gather ----------------------
__global__ void k_gather(const void* __restrict__ inp, const float* __restrict__ emb){
    int r = blockIdx.x;
    int s = r >> 6, b = r & 63;
    int idx = load_idx(inp, b*SS + s, g_in64);
    int f = threadIdx.x * 4;
    float4 v = make_float4(0.f,0.f,0.f,0.f);
    if (idx != 0) v = *(const float4*)(emb + (size_t)idx*FF + f);   // padding_idx row -> 0
    *(float4*)(g_V + (size_t)r*FF + f) = v;
}

// ------------------------- generic tiled fp32 GEMM --------------------------
// C[M,N] = A[M,K] * B   (A row-major, K contiguous)
// KMAJ=true : B is [N,K] with K contiguous  (C = A * B^T)
// KMAJ=false: B is [K,N] with N contiguous  (C = A * B)
// EPI: 0 = +bias ; 1 = relu(+bias)
template<int EPI, bool KMAJ>
__global__ void __launch_bounds__(256) k_gemm(
        const float* __restrict__ A, const float* __restrict__ Bm,
        const float* __restrict__ bias, float* __restrict__ C,
        int M, int N, int K)
{
    const int BK = 16;
    __shared__ __align__(16) float As[BK][128];
    __shared__ __align__(16) float Bs[BK][128];

    int tid = threadIdx.x;
    int n0 = blockIdx.x * 128;
    int m0 = blockIdx.y * 128;
    int tx = tid & 15, ty = tid >> 4;

    int a_m = tid >> 2;            // 0..63
    int a_k = (tid & 3) << 2;      // 0,4,8,12
    int bn_k = tid >> 5;           // 0..7   (NN loader)
    int bn_n = (tid & 31) << 2;    // 0..124

    float4 ar[2], br[2];
    {
        const float* Ap = A + (size_t)(m0 + a_m)*K + a_k;
        ar[0] = *(const float4*)Ap;
        ar[1] = *(const float4*)(Ap + (size_t)64*K);
        if (KMAJ){
            const float* Bp = Bm + (size_t)(n0 + a_m)*K + a_k;
            br[0] = *(const float4*)Bp;
            br[1] = *(const float4*)(Bp + (size_t)64*K);
        } else {
            const float* Bp = Bm + (size_t)bn_k*N + n0 + bn_n;
            br[0] = *(const float4*)Bp;
            br[1] = *(const float4*)(Bp + (size_t)8*N);
        }
    }

    unsigned long long acc[8][4];
    #pragma unroll
    for (int i=0;i<8;i++)
        #pragma unroll
        for (int j=0;j<4;j++) acc[i][j] = 0ull;

    for (int kt = 0; kt < K; kt += BK){
        As[a_k+0][a_m]    = ar[0].x; As[a_k+1][a_m]    = ar[0].y;
        As[a_k+2][a_m]    = ar[0].z; As[a_k+3][a_m]    = ar[0].w;
        As[a_k+0][a_m+64] = ar[1].x; As[a_k+1][a_m+64] = ar[1].y;
        As[a_k+2][a_m+64] = ar[1].z; As[a_k+3][a_m+64] = ar[1].w;
        if (KMAJ){
            Bs[a_k+0][a_m]    = br[0].x; Bs[a_k+1][a_m]    = br[0].y;
            Bs[a_k+2][a_m]    = br[0].z; Bs[a_k+3][a_m]    = br[0].w;
            Bs[a_k+0][a_m+64] = br[1].x; Bs[a_k+1][a_m+64] = br[1].y;
            Bs[a_k+2][a_m+64] = br[1].z; Bs[a_k+3][a_m+64] = br[1].w;
        } else {
            *(float4*)&Bs[bn_k  ][bn_n] = br[0];
            *(float4*)&Bs[bn_k+8][bn_n] = br[1];
        }
        __syncthreads();

        if (kt + BK < K){   // software pipeline: prefetch next slab into regs
            const float* Ap = A + (size_t)(m0 + a_m)*K + (kt + BK) + a_k;
            ar[0] = *(const float4*)Ap;
            ar[1] = *(const float4*)(Ap + (size_t)64*K);
            if (KMAJ){
                const float* Bp = Bm + (size_t)(n0 + a_m)*K + (kt + BK) + a_k;
                br[0] = *(const float4*)Bp;
                br[1] = *(const float4*)(Bp + (size_t)64*K);
            } else {
                const float* Bp = Bm + (size_t)(kt + BK + bn_k)*N + n0 + bn_n;
                br[0] = *(const float4*)Bp;
                br[1] = *(const float4*)(Bp + (size_t)8*N);
            }
        }

        #pragma unroll
        for (int k = 0; k < BK; k++){
            float4 a0 = *(const float4*)&As[k][ty*8];
            float4 a1 = *(const float4*)&As[k][ty*8+4];
            float4 b0 = *(const float4*)&Bs[k][tx*8];
            float4 b1 = *(const float4*)&Bs[k][tx*8+4];
            unsigned long long b2[4] = {
                pack2(b0.x,b0.y), pack2(b0.z,b0.w),
                pack2(b1.x,b1.y), pack2(b1.z,b1.w) };
            float a[8] = {a0.x,a0.y,a0.z,a0.w,a1.x,a1.y,a1.z,a1.w};
            #pragma unroll
            for (int i=0;i<8;i++){
                unsigned long long ad = pack2(a[i], a[i]);
                #pragma unroll
                for (int j=0;j<4;j++) fma2(acc[i][j], ad, b2[j]);
            }
        }
        __syncthreads();
    }

    float bv[8];
    #pragma unroll
    for (int j=0;j<8;j++) bv[j] = bias[n0 + tx*8 + j];
    #pragma unroll
    for (int i=0;i<8;i++){
        int m = m0 + ty*8 + i;
        float o[8];
        #pragma unroll
        for (int j=0;j<4;j++){
            float2 t = unpack2(acc[i][j]);
            o[2*j]   = t.x + bv[2*j];
            o[2*j+1] = t.y + bv[2*j+1];
        }
        if (EPI == 1){
            #pragma unroll
            for (int j=0;j<8;j++) o[j] = fmaxf(o[j], 0.f);
        }
        float* cp = C + (size_t)m*N + n0 + tx*8;
        *(float4*)cp       = make_float4(o[0],o[1],o[2],o[3]);
        *(float4*)(cp + 4) = make_float4(o[4],o[5],o[6],o[7]);
    }
}

// ------------------------- bf16 tensor-core logits GEMM ---------------------
// logits[m,n] = (g_Oh[m,:] . g_embh[n,:]) * INV_SQRT_F
// Streams exp() row-sums into g_se (column 0 excluded; pre-seeded with 1.0).
// Block tile 128(M) x 256(N) x 32(K); 8 warps, warp tile 64x64, mma.m16n8k16.
__global__ void __launch_bounds__(256) k_hgemm_logits(
        const __nv_bfloat16* __restrict__ A,   // [RT, FF]
        const __nv_bfloat16* __restrict__ B)   // [VV, FF]
{
    const int PITCH = 40;   // 32 + 8 halves: conflict-free fragment LDS
    __shared__ __align__(16) __nv_bfloat16 As[128*PITCH];
    __shared__ __align__(16) __nv_bfloat16 Bs[256*PITCH];

    int tid  = threadIdx.x;
    int lane = tid & 31, wid = tid >> 5;
    int wm = wid >> 2, wn = wid & 3;       // 2 x 4 warps
    int g  = lane >> 2, t = lane & 3;
    int m0 = blockIdx.y * 128;
    int n0 = blockIdx.x * 256;

    int a_r = tid >> 1;                    // 0..127
    int a_c = (tid & 1) * 2;               // chunk pair base {0,2}
    int b_r = tid;                         // 0..255

    uint4 ar[2], br[4];
    {
        const __nv_bfloat16* Ag = A + (size_t)(m0 + a_r)*FF + a_c*8;
        const __nv_bfloat16* Bg = B + (size_t)(n0 + b_r)*FF;
        ar[0] = *(const uint4*)(Ag);
        ar[1] = *(const uint4*)(Ag + 8);
        #pragma unroll
        for (int c=0;c<4;c++) br[c] = *(const uint4*)(Bg + c*8);
    }

    float acc[4][8][4];
    #pragma unroll
    for (int i=0;i<4;i++)
        #pragma unroll
        for (int j=0;j<8;j++)
            #pragma unroll
            for (int q=0;q<4;q++) acc[i][j][q] = 0.f;

    for (int kt = 0; kt < FF; kt += 32){
        *(uint4*)&As[a_r*PITCH + a_c*8]     = ar[0];
        *(uint4*)&As[a_r*PITCH + a_c*8 + 8] = ar[1];
        #pragma unroll
        for (int c=0;c<4;c++) *(uint4*)&Bs[b_r*PITCH + c*8] = br[c];
        __syncthreads();

        if (kt + 32 < FF){
            const __nv_bfloat16* Ag = A + (size_t)(m0 + a_r)*FF + (kt+32) + a_c*8;
            const __nv_bfloat16* Bg = B + (size_t)(n0 + b_r)*FF + (kt+32);
            ar[0] = *(const uint4*)(Ag);
            ar[1] = *(const uint4*)(Ag + 8);
            #pragma unroll
            for (int c=0;c<4;c++) br[c] = *(const uint4*)(Bg + c*8);
        }

        #pragma unroll
        for (int ks = 0; ks < 32; ks += 16){
            uint32_t af[4][4], bf[8][2];
            #pragma unroll
            for (int mf=0; mf<4; mf++){
                int row  = wm*64 + mf*16 + g;
                int base = row*PITCH + ks + t*2;
                af[mf][0] = *(const uint32_t*)&As[base];
                af[mf][1] = *(const uint32_t*)&As[base + 8*PITCH];
                af[mf][2] = *(const uint32_t*)&As[base + 8];
                af[mf][3] = *(const uint32_t*)&As[base + 8*PITCH + 8];
            }
            #pragma unroll
            for (int nf=0; nf<8; nf++){
                int coln = wn*64 + nf*8 + g;
                int base = coln*PITCH + ks + t*2;
                bf[nf][0] = *(const uint32_t*)&Bs[base];
                bf[nf][1] = *(const uint32_t*)&Bs[base + 8];
            }
            #pragma unroll
            for (int mf=0; mf<4; mf++)
                #pragma unroll
                for (int nf=0; nf<8; nf++)
                    mma_bf16(acc[mf][nf], af[mf], bf[nf]);
        }
        __syncthreads();
    }

    // epilogue: exp + per-row partial sum -> atomics into g_se
    #pragma unroll
    for (int mf=0; mf<4; mf++){
        float rlo = 0.f, rhi = 0.f;
        #pragma unroll
        for (int nf=0; nf<8; nf++){
            int nb = n0 + wn*64 + nf*8 + t*2;
            float e0 = __expf(acc[mf][nf][0]*INV_SQRT_F);
            float e1 = __expf(acc[mf][nf][1]*INV_SQRT_F);
            float e2 = __expf(acc[mf][nf][2]*INV_SQRT_F);
            float e3 = __expf(acc[mf][nf][3]*INV_SQRT_F);
            if (nb == 0){ e0 = 0.f; e2 = 0.f; }   // column 0 excluded (handled in g_se init)
            rlo += e0 + e1;
            rhi += e2 + e3;
        }
        rlo += __shfl_xor_sync(0xffffffffu, rlo, 1);
        rlo += __shfl_xor_sync(0xffffffffu, rlo, 2);
        rhi += __shfl_xor_sync(0xffffffffu, rhi, 1);
        rhi += __shfl_xor_sync(0xffffffffu, rhi, 2);
        if (t == 0){
            int row = m0 + wm*64 + mf*16 + g;
            atomicAdd(&g_se[row],     rlo);
            atomicAdd(&g_se[row + 8], rhi);
        }
    }
}

// ------------------------- recurrence: one step -----------------------------
// gate = sigmoid(P[s] + state @ see[F:2F, :]);  C[s] = state*gate + vecs*(1-gate)
__global__ void __launch_bounds__(256) k_recurr(const float* __restrict__ see, int s){
    __shared__ float Ssm[64][129];  // state chunk [b][k], padded
    __shared__ float Bsm[128][8];   // see_bot chunk [k][j]
    int tid = threadIdx.x;
    int j0 = blockIdx.x * 8;
    int b  = tid & 63;
    int jg = tid >> 6;              // 0..3

    float acc0 = 0.f, acc1 = 0.f;
    if (s > 0){
        const float* st = g_C + (size_t)(s-1)*BB*FF;
        for (int kc = 0; kc < FF; kc += 128){
            for (int t = tid*4; t < 64*128; t += 1024){
                int br = t >> 7, k = t & 127;
                float4 v = *(const float4*)(st + (size_t)br*FF + kc + k);
                Ssm[br][k] = v.x; Ssm[br][k+1] = v.y; Ssm[br][k+2] = v.z; Ssm[br][k+3] = v.w;
            }
            {
                int k = tid >> 1, jj = (tid & 1) * 4;
                float4 v = *(const float4*)(see + (size_t)(FF + kc + k)*FF + j0 + jj);
                Bsm[k][jj] = v.x; Bsm[k][jj+1] = v.y; Bsm[k][jj+2] = v.z; Bsm[k][jj+3] = v.w;
            }
            __syncthreads();
            #pragma unroll 8
            for (int k = 0; k < 128; k++){
                float sv = Ssm[b][k];
                acc0 = fmaf(sv, Bsm[k][jg],   acc0);
                acc1 = fmaf(sv, Bsm[k][jg+4], acc1);
            }
            __syncthreads();
        }
    }
    size_t ro = ((size_t)s*BB + b)*FF;
    {
        int j = j0 + jg;
        float g1 = 1.f / (1.f + expf(-(g_P[ro + j] + acc0)));
        float sv = (s > 0) ? g_C[ro - (size_t)BB*FF + j] : 0.f;
        float vv = g_V[ro + j];
        g_C[ro + j] = sv*g1 + vv*(1.f - g1);
    }
    {
        int j = j0 + jg + 4;
        float g1 = 1.f / (1.f + expf(-(g_P[ro + j] + acc1)));
        float sv = (s > 0) ? g_C[ro - (size_t)BB*FF + j] : 0.f;
        float vv = g_V[ro + j];
        g_C[ro + j] = sv*g1 + vv*(1.f - g1);
    }
}

// ------------------------- layernorm (writes into g_P) ----------------------
__global__ void __launch_bounds__(128) k_ln(const float* __restrict__ gam, const float* __restrict__ bet){
    int r = blockIdx.x;
    const float* x = g_C + (size_t)r*FF;
    float*       y = g_P + (size_t)r*FF;
    int tid = threadIdx.x;
    float4 v = *(const float4*)(x + tid*4);
    float s = v.x + v.y + v.z + v.w;
    float q = v.x*v.x + v.y*v.y + v.z*v.z + v.w*v.w;
    #pragma unroll
    for (int off = 16; off; off >>= 1){
        s += __shfl_down_sync(0xffffffffu, s, off);
        q += __shfl_down_sync(0xffffffffu, q, off);
    }
    __shared__ float ss[4], qq[4];
    int w = tid >> 5, lane = tid & 31;
    if (lane == 0){ ss[w] = s; qq[w] = q; }
    __syncthreads();
    float S = ss[0]+ss[1]+ss[2]+ss[3];
    float Q = qq[0]+qq[1]+qq[2]+qq[3];
    float mu  = S * (1.f/FF);
    float var = Q * (1.f/FF) - mu*mu;
    float rstd = rsqrtf(var + 1e-5f);
    float4 gg = *(const float4*)(gam + tid*4);
    float4 bb = *(const float4*)(bet + tid*4);
    float4 o;
    o.x = (v.x - mu)*rstd*gg.x + bb.x;
    o.y = (v.y - mu)*rstd*gg.y + bb.y;
    o.z = (v.z - mu)*rstd*gg.z + bb.z;
    o.w = (v.w - mu)*rstd*gg.w + bb.w;
    *(float4*)(y + tid*4) = o;
}

// ------------------------- target logit + sumexp init -----------------------
__global__ void __launch_bounds__(256) k_tgt(const void* __restrict__ tg, const float* __restrict__ emb){
    int tid = threadIdx.x, lane = tid & 31, w = tid >> 5;
    int r = blockIdx.x * 8 + w;
    int s = r >> 6, b = r & 63;
    int t = load_idx(tg, b*SS + s, g_tg64);
    float dot = 0.f;
    if (t != 0){
        const float4* o = (const float4*)(g_O + (size_t)r*FF);
        const float4* e = (const float4*)(emb + (size_t)t*FF);
        #pragma unroll
        for (int it = 0; it < 4; it++){
            float4 ov = o[lane + 32*it];
            float4 ev = e[lane + 32*it];
            dot += ov.x*ev.x + ov.y*ev.y + ov.z*ev.z + ov.w*ev.w;
        }
    }
    #pragma unroll
    for (int off = 16; off; off >>= 1) dot += __shfl_down_sync(0xffffffffu, dot, off);
    if (lane == 0){
        g_tl[r]   = dot * INV_SQRT_F;
        g_mask[r] = (t != 0) ? 1.f : 0.f;
        g_se[r]   = 1.f;   // exp(logit[v=0]) = exp(0): emb_m row 0 is zero
    }
}

// ------------------------- per-step loss + global mean -----------------------
__global__ void __launch_bounds__(64) k_loss(float* __restrict__ out){
    int s = blockIdx.x, b = threadIdx.x;
    int r = s*BB + b;
    float m   = g_mask[r];
    float nll = (logf(g_se[r]) - g_tl[r]) * m;
    float nn = nll, mm = m;
    #pragma unroll
    for (int off = 16; off; off >>= 1){
        nn += __shfl_down_sync(0xffffffffu, nn, off);
        mm += __shfl_down_sync(0xffffffffu, mm, off);
    }
    __shared__ float sn[2], sm[2];
    if ((b & 31) == 0){ sn[b>>5] = nn; sm[b>>5] = mm; }
    __syncthreads();
    if (b == 0){
        float N_ = sn[0] + sn[1], M_ = sm[0] + sm[1];
        atomicAdd(out, (N_ / fmaxf(M_, 1.f)) * (1.f/SS));
    }
}

// ------------------------- launch -------------------------------------------
extern "C" void kernel_launch(void* const* d_in, const int* in_sizes, int n_in,
                              void* d_out, int out_size){
    const void*  inp   = d_in[0];
    const void*  tgt   = d_in[1];
    const float* see   = (const float*)d_in[2];
    const float* bias  = (const float*)d_in[3];
    const float* W_in  = (const float*)d_in[4];
    const float* b_in  = (const float*)d_in[5];
    const float* W_out = (const float*)d_in[6];
    const float* b_out = (const float*)d_in[7];
    const float* ln_g  = (const float*)d_in[8];
    const float* ln_b  = (const float*)d_in[9];
    const float* emb   = (const float*)d_in[10];
    float* out = (float*)d_out;

    void *pV, *pP, *pC, *pH, *pO, *pOh, *pEh;
    cudaGetSymbolAddress(&pV, g_V);
    cudaGetSymbolAddress(&pP, g_P);
    cudaGetSymbolAddress(&pC, g_C);
    cudaGetSymbolAddress(&pH, g_H);
    cudaGetSymbolAddress(&pO, g_O);
    cudaGetSymbolAddress(&pOh, g_Oh);
    cudaGetSymbolAddress(&pEh, g_embh);

    k_init<<<1, 256>>>((const int*)inp, (const int*)tgt, out);
    k_cvt_emb<<<(int)(((size_t)VV*FF)/1024), 256>>>(emb);
    k_gather<<<RT, 128>>>(inp, emb);

    // P = Vecs @ see_top + bias      (B is [K,N] n-contiguous)
    k_gemm<0,false><<<dim3(FF/128, RT/128), 256>>>((const float*)pV, see, bias, (float*)pP, RT, FF, FF);

    for (int s = 0; s < SS; s++)
        k_recurr<<<FF/8, 256>>>(see, s);

    k_ln<<<RT, 128>>>(ln_g, ln_b);    // Y -> g_P (reuse)

    // H = relu(Y @ W_in^T + b_in)
    k_gemm<1,true><<<dim3(HH/128, RT/128), 256>>>((const float*)pP, W_in, b_in, (float*)pH, RT, HH, FF);
    // O = H @ W_out^T + b_out
    k_gemm<0,true><<<dim3(FF/128, RT/128), 256>>>((const float*)pH, W_out, b_out, (float*)pO, RT, FF, HH);

    k_cvt_O<<<(int)(((size_t)RT*FF)/1024), 256>>>();
    k_tgt<<<RT/8, 256>>>(tgt, emb);

    // logits + streamed sum-exp on tensor cores (no logits buffer)
    k_hgemm_logits<<<dim3(VV/256, RT/128), 256>>>(
        (const __nv_bfloat16*)pOh, (const __nv_bfloat16*)pEh);

    k_loss<<<SS, 64>>>(out);
}

// round 17
// speedup vs baseline: 2.9577x; 1.5132x over previous
#include <cuda_runtime.h>
#include <cuda_bf16.h>
#include <math.h>
#include <stdint.h>

#define SS 256
#define BB 64
#define FF 512
#define HH 2048
#define VV 32000
#define RT (SS*BB)   // 16384 rows (s-major: r = s*64 + b)

// ------------------------- scratch (device globals; no allocs) -------------
__device__ float g_V[(size_t)RT*FF];   // gathered embeddings
__device__ float g_P[(size_t)RT*FF];   // vecs@see_top + bias
__device__ float g_C[(size_t)RT*FF];   // cont (state history)
__device__ float g_O[(size_t)RT*FF];   // MLP output (fp32, for exact target logit)
__device__ __nv_bfloat16 g_embh[(size_t)VV*FF];  // bf16 emb (row 0 zeroed)
__device__ __nv_bfloat16 g_Oh[(size_t)RT*FF];    // bf16 O
__device__ __nv_bfloat16 g_Yh[(size_t)RT*FF];    // bf16 LN output
__device__ __nv_bfloat16 g_Hh[(size_t)RT*HH];    // bf16 hidden
__device__ __nv_bfloat16 g_Winh[(size_t)HH*FF];
__device__ __nv_bfloat16 g_Wouth[(size_t)FF*HH];
__device__ float g_se[RT];             // sum of exp(logits)
__device__ float g_tl[RT];             // target logit
__device__ float g_mask[RT];
__device__ int   g_in64, g_tg64;
__device__ unsigned g_bar;             // inter-CTA barrier counter (reset each launch)

#define INV_SQRT_F 0.044194173824159216f

// ------------------------- small helpers -----------------------------------
__device__ __forceinline__ unsigned long long pack2(float lo, float hi){
    unsigned long long r;
    asm("mov.b64 %0, {%1, %2};" : "=l"(r) : "f"(lo), "f"(hi));
    return r;
}
__device__ __forceinline__ void fma2(unsigned long long &acc, unsigned long long a, unsigned long long b){
    asm("fma.rn.f32x2 %0, %1, %2, %0;" : "+l"(acc) : "l"(a), "l"(b));
}
__device__ __forceinline__ float2 unpack2(unsigned long long v){
    float2 r;
    asm("mov.b64 {%0, %1}, %2;" : "=f"(r.x), "=f"(r.y) : "l"(v));
    return r;
}
__device__ __forceinline__ int load_idx(const void* p, int pos, int is64){
    if (is64) return (int)((const long long*)p)[pos];
    return ((const int*)p)[pos];
}
__device__ __forceinline__ void mma_bf16(float* c, const uint32_t* a, const uint32_t* b){
    asm volatile("mma.sync.aligned.m16n8k16.row.col.f32.bf16.bf16.f32 "
        "{%0,%1,%2,%3}, {%4,%5,%6,%7}, {%8,%9}, {%0,%1,%2,%3};"
        : "+f"(c[0]), "+f"(c[1]), "+f"(c[2]), "+f"(c[3])
        : "r"(a[0]), "r"(a[1]), "r"(a[2]), "r"(a[3]), "r"(b[0]), "r"(b[1]));
}

// ------------------------- kernel 0: init + dtype detect -------------------
__global__ void k_init(const int* inw, const int* tgw, float* out){
    __shared__ int f0, f1;
    int tid = threadIdx.x;
    if (tid == 0){ f0 = 1; f1 = 1; out[0] = 0.f; g_bar = 0u; }
    __syncthreads();
    for (int p = tid; p < RT; p += blockDim.x){
        if (p & 1){
            if (inw[p] != 0) f0 = 0;
            if (tgw[p] != 0) f1 = 0;
        }
    }
    __syncthreads();
    if (tid == 0){ g_in64 = f0; g_tg64 = f1; }
}

// ------------------------- bf16 conversions ---------------------------------
__global__ void k_cvt_emb(const float* __restrict__ emb){
    size_t i = ((size_t)blockIdx.x*256 + threadIdx.x)*4;
    float4 v = *(const float4*)(emb + i);
    if (i < FF) v = make_float4(0.f,0.f,0.f,0.f);   // padding row 0 -> emb_m
    __nv_bfloat162 h0 = __float22bfloat162_rn(make_float2(v.x, v.y));
    __nv_bfloat162 h1 = __float22bfloat162_rn(make_float2(v.z, v.w));
    uint2 o = make_uint2(*(unsigned*)&h0, *(unsigned*)&h1);
    *(uint2*)(g_embh + i) = o;
}
__global__ void k_cvt(const float* __restrict__ src, __nv_bfloat16* __restrict__ dst){
    size_t i = ((size_t)blockIdx.x*256 + threadIdx.x)*4;
    float4 v = *(const float4*)(src + i);
    __nv_bfloat162 h0 = __float22bfloat162_rn(make_float2(v.x, v.y));
    __nv_bfloat162 h1 = __float22bfloat162_rn(make_float2(v.z, v.w));
    uint2 o = make_uint2(*(unsigned*)&h0, *(unsigned*)&h1);
    *(uint2*)(dst + i) = o;
}

// ------------------------- embedding gather ---------------------------------
__global__ void k_gather(const void* __restrict__ inp, const float* __restrict__ emb){
    int r = blockIdx.x;
    int s = r >> 6, b = r & 63;
    int idx = load_idx(inp, b*SS + s, g_in64);
    int f = threadIdx.x * 4;
    float4 v = make_float4(0.f,0.f,0.f,0.f);
    if (idx != 0) v = *(const float4*)(emb + (size_t)idx*FF + f);
    *(float4*)(g_V + (size_t)r*FF + f) = v;
}

// ------------------------- fp32 tiled GEMM (only for P = V @ see_top) -------
__global__ void __launch_bounds__(256) k_gemm_nn(
        const float* __restrict__ A, const float* __restrict__ Bm,
        const float* __restrict__ bias, float* __restrict__ C,
        int M, int N, int K)
{
    const int BK = 16;
    __shared__ __align__(16) float As[BK][128];
    __shared__ __align__(16) float Bs[BK][128];

    int tid = threadIdx.x;
    int n0 = blockIdx.x * 128;
    int m0 = blockIdx.y * 128;
    int tx = tid & 15, ty = tid >> 4;

    int a_m = tid >> 2;
    int a_k = (tid & 3) << 2;
    int bn_k = tid >> 5;
    int bn_n = (tid & 31) << 2;

    float4 ar[2], br[2];
    {
        const float* Ap = A + (size_t)(m0 + a_m)*K + a_k;
        ar[0] = *(const float4*)Ap;
        ar[1] = *(const float4*)(Ap + (size_t)64*K);
        const float* Bp = Bm + (size_t)bn_k*N + n0 + bn_n;
        br[0] = *(const float4*)Bp;
        br[1] = *(const float4*)(Bp + (size_t)8*N);
    }

    unsigned long long acc[8][4];
    #pragma unroll
    for (int i=0;i<8;i++)
        #pragma unroll
        for (int j=0;j<4;j++) acc[i][j] = 0ull;

    for (int kt = 0; kt < K; kt += BK){
        As[a_k+0][a_m]    = ar[0].x; As[a_k+1][a_m]    = ar[0].y;
        As[a_k+2][a_m]    = ar[0].z; As[a_k+3][a_m]    = ar[0].w;
        As[a_k+0][a_m+64] = ar[1].x; As[a_k+1][a_m+64] = ar[1].y;
        As[a_k+2][a_m+64] = ar[1].z; As[a_k+3][a_m+64] = ar[1].w;
        *(float4*)&Bs[bn_k  ][bn_n] = br[0];
        *(float4*)&Bs[bn_k+8][bn_n] = br[1];
        __syncthreads();

        if (kt + BK < K){
            const float* Ap = A + (size_t)(m0 + a_m)*K + (kt + BK) + a_k;
            ar[0] = *(const float4*)Ap;
            ar[1] = *(const float4*)(Ap + (size_t)64*K);
            const float* Bp = Bm + (size_t)(kt + BK + bn_k)*N + n0 + bn_n;
            br[0] = *(const float4*)Bp;
            br[1] = *(const float4*)(Bp + (size_t)8*N);
        }

        #pragma unroll
        for (int k = 0; k < BK; k++){
            float4 a0 = *(const float4*)&As[k][ty*8];
            float4 a1 = *(const float4*)&As[k][ty*8+4];
            float4 b0 = *(const float4*)&Bs[k][tx*8];
            float4 b1 = *(const float4*)&Bs[k][tx*8+4];
            unsigned long long b2[4] = {
                pack2(b0.x,b0.y), pack2(b0.z,b0.w),
                pack2(b1.x,b1.y), pack2(b1.z,b1.w) };
            float a[8] = {a0.x,a0.y,a0.z,a0.w,a1.x,a1.y,a1.z,a1.w};
            #pragma unroll
            for (int i=0;i<8;i++){
                unsigned long long ad = pack2(a[i], a[i]);
                #pragma unroll
                for (int j=0;j<4;j++) fma2(acc[i][j], ad, b2[j]);
            }
        }
        __syncthreads();
    }

    float bv[8];
    #pragma unroll
    for (int j=0;j<8;j++) bv[j] = bias[n0 + tx*8 + j];
    #pragma unroll
    for (int i=0;i<8;i++){
        int m = m0 + ty*8 + i;
        float o[8];
        #pragma unroll
        for (int j=0;j<4;j++){
            float2 t = unpack2(acc[i][j]);
            o[2*j]   = t.x + bv[2*j];
            o[2*j+1] = t.y + bv[2*j+1];
        }
        float* cp = C + (size_t)m*N + n0 + tx*8;
        *(float4*)cp       = make_float4(o[0],o[1],o[2],o[3]);
        *(float4*)(cp + 4) = make_float4(o[4],o[5],o[6],o[7]);
    }
}

// ------------------------- persistent recurrence -----------------------------
// 64 CTAs x 128 threads. CTA owns 8 gate columns [j0, j0+8); see_bot slice held
// in smem for all 256 steps. Per step: stream state via __ldcg, compute gates,
// write C[s], global release-barrier.
__global__ void __launch_bounds__(128) k_recurr_all(const float* __restrict__ see){
    __shared__ float Ssm[64*68];                  // 64 rows x 64-k chunk, pitch 68
    __shared__ __align__(16) float4 Bsm4[2][512]; // [jg][k] = see_bot cols {jg, jg+2, jg+4, jg+6}

    int tid = threadIdx.x;
    int j0  = blockIdx.x * 8;
    int b   = tid & 63;
    int jg  = tid >> 6;                 // 0..1

    for (int idx = tid; idx < 2*512; idx += 128){
        int jj = idx >> 9, k = idx & 511;
        const float* sp = see + (size_t)(FF + k)*FF + j0 + jj;
        Bsm4[jj][k] = make_float4(sp[0], sp[2], sp[4], sp[6]);
    }
    __syncthreads();

    float prev[4] = {0.f, 0.f, 0.f, 0.f};

    for (int s = 0; s < SS; s++){
        size_t ro = ((size_t)s*BB + b)*FF;
        float pv[4], vv[4];
        #pragma unroll
        for (int q=0;q<4;q++){
            int j = j0 + jg + 2*q;
            pv[q] = g_P[ro + j];
            vv[q] = g_V[ro + j];
        }

        unsigned long long acc01 = 0ull, acc23 = 0ull;
        if (s > 0){
            const float* st = g_C + (size_t)(s-1)*BB*FF;
            float4 pre[8];
            #pragma unroll
            for (int i=0;i<8;i++){
                int fidx = tid + i*128;
                int row = fidx >> 4, c4 = fidx & 15;
                pre[i] = __ldcg((const float4*)(st + (size_t)row*FF + c4*4));
            }
            #pragma unroll 1
            for (int c = 0; c < 8; c++){
                #pragma unroll
                for (int i=0;i<8;i++){
                    int fidx = tid + i*128;
                    int row = fidx >> 4, c4 = fidx & 15;
                    *(float4*)&Ssm[row*68 + c4*4] = pre[i];
                }
                __syncthreads();
                if (c < 7){
                    #pragma unroll
                    for (int i=0;i<8;i++){
                        int fidx = tid + i*128;
                        int row = fidx >> 4, c4 = fidx & 15;
                        pre[i] = __ldcg((const float4*)(st + (size_t)row*FF + (c+1)*64 + c4*4));
                    }
                }
                const float4* Sp = (const float4*)&Ssm[b*68];
                const float4* Bp = &Bsm4[jg][c*64];
                #pragma unroll
                for (int kk = 0; kk < 16; kk++){
                    float4 s4 = Sp[kk];
                    float4 b0 = Bp[4*kk+0], b1 = Bp[4*kk+1], b2 = Bp[4*kk+2], b3 = Bp[4*kk+3];
                    unsigned long long sx;
                    sx = pack2(s4.x, s4.x);
                    fma2(acc01, sx, pack2(b0.x,b0.y)); fma2(acc23, sx, pack2(b0.z,b0.w));
                    sx = pack2(s4.y, s4.y);
                    fma2(acc01, sx, pack2(b1.x,b1.y)); fma2(acc23, sx, pack2(b1.z,b1.w));
                    sx = pack2(s4.z, s4.z);
                    fma2(acc01, sx, pack2(b2.x,b2.y)); fma2(acc23, sx, pack2(b2.z,b2.w));
                    sx = pack2(s4.w, s4.w);
                    fma2(acc01, sx, pack2(b3.x,b3.y)); fma2(acc23, sx, pack2(b3.z,b3.w));
                }
                __syncthreads();
            }
        }

        float2 a01 = unpack2(acc01), a23 = unpack2(acc23);
        float av[4] = {a01.x, a01.y, a23.x, a23.y};
        #pragma unroll
        for (int q=0;q<4;q++){
            int j = j0 + jg + 2*q;
            float g1 = 1.f/(1.f + expf(-(pv[q] + av[q])));
            float nc = prev[q]*g1 + vv[q]*(1.f - g1);
            prev[q] = nc;
            g_C[ro + j] = nc;
        }

        if (s < SS-1){
            __threadfence();          // release C[s] stores to L2 before arriving
            __syncthreads();
            if (tid == 0){
                unsigned arrived = atomicAdd(&g_bar, 1u) + 1u;
                unsigned want = 64u*(unsigned)(s+1);
                while (arrived < want) arrived = *(volatile unsigned*)&g_bar;
            }
            __syncthreads();          // readers use __ldcg (L2) next step
        }
    }
}

// ------------------------- layernorm (bf16 out) ------------------------------
__global__ void __launch_bounds__(128) k_ln(const float* __restrict__ gam, const float* __restrict__ bet){
    int r = blockIdx.x;
    const float* x = g_C + (size_t)r*FF;
    int tid = threadIdx.x;
    float4 v = *(const float4*)(x + tid*4);
    float s = v.x + v.y + v.z + v.w;
    float q = v.x*v.x + v.y*v.y + v.z*v.z + v.w*v.w;
    #pragma unroll
    for (int off = 16; off; off >>= 1){
        s += __shfl_down_sync(0xffffffffu, s, off);
        q += __shfl_down_sync(0xffffffffu, q, off);
    }
    __shared__ float ss[4], qq[4];
    int w = tid >> 5, lane = tid & 31;
    if (lane == 0){ ss[w] = s; qq[w] = q; }
    __syncthreads();
    float S = ss[0]+ss[1]+ss[2]+ss[3];
    float Q = qq[0]+qq[1]+qq[2]+qq[3];
    float mu  = S * (1.f/FF);
    float var = Q * (1.f/FF) - mu*mu;
    float rstd = rsqrtf(var + 1e-5f);
    float4 gg = *(const float4*)(gam + tid*4);
    float4 bb = *(const float4*)(bet + tid*4);
    float ox = (v.x - mu)*rstd*gg.x + bb.x;
    float oy = (v.y - mu)*rstd*gg.y + bb.y;
    float oz = (v.z - mu)*rstd*gg.z + bb.z;
    float ow = (v.w - mu)*rstd*gg.w + bb.w;
    __nv_bfloat162 h0 = __float22bfloat162_rn(make_float2(ox, oy));
    __nv_bfloat162 h1 = __float22bfloat162_rn(make_float2(oz, ow));
    uint2 o = make_uint2(*(unsigned*)&h0, *(unsigned*)&h1);
    *(uint2*)(g_Yh + (size_t)r*FF + tid*4) = o;
}

// ------------------------- generic bf16 HMMA GEMM ----------------------------
// C[M,N] = A[M,K] @ B[N,K]^T + bias.  EPI 0: relu -> bf16 Cb.
//                                     EPI 1: bf16 Cb AND fp32 Cf.
// Block tile 128(M) x 256(N) x 32(K); 8 warps, warp tile 64x64.
template<int EPI>
__global__ void __launch_bounds__(256) k_hgemm(
        const __nv_bfloat16* __restrict__ A, const __nv_bfloat16* __restrict__ B,
        const float* __restrict__ bias, __nv_bfloat16* __restrict__ Cb,
        float* __restrict__ Cf, int N, int K)
{
    const int PITCH = 40;
    __shared__ __align__(16) __nv_bfloat16 As[128*PITCH];
    __shared__ __align__(16) __nv_bfloat16 Bs[256*PITCH];

    int tid  = threadIdx.x;
    int lane = tid & 31, wid = tid >> 5;
    int wm = wid >> 2, wn = wid & 3;
    int g  = lane >> 2, t = lane & 3;
    int m0 = blockIdx.y * 128;
    int n0 = blockIdx.x * 256;

    int a_r = tid >> 1;
    int a_c = (tid & 1) * 2;
    int b_r = tid;

    uint4 ar[2], br[4];
    {
        const __nv_bfloat16* Ag = A + (size_t)(m0 + a_r)*K + a_c*8;
        const __nv_bfloat16* Bg = B + (size_t)(n0 + b_r)*K;
        ar[0] = *(const uint4*)(Ag);
        ar[1] = *(const uint4*)(Ag + 8);
        #pragma unroll
        for (int c=0;c<4;c++) br[c] = *(const uint4*)(Bg + c*8);
    }

    float acc[4][8][4];
    #pragma unroll
    for (int i=0;i<4;i++)
        #pragma unroll
        for (int j=0;j<8;j++)
            #pragma unroll
            for (int q=0;q<4;q++) acc[i][j][q] = 0.f;

    for (int kt = 0; kt < K; kt += 32){
        *(uint4*)&As[a_r*PITCH + a_c*8]     = ar[0];
        *(uint4*)&As[a_r*PITCH + a_c*8 + 8] = ar[1];
        #pragma unroll
        for (int c=0;c<4;c++) *(uint4*)&Bs[b_r*PITCH + c*8] = br[c];
        __syncthreads();

        if (kt + 32 < K){
            const __nv_bfloat16* Ag = A + (size_t)(m0 + a_r)*K + (kt+32) + a_c*8;
            const __nv_bfloat16* Bg = B + (size_t)(n0 + b_r)*K + (kt+32);
            ar[0] = *(const uint4*)(Ag);
            ar[1] = *(const uint4*)(Ag + 8);
            #pragma unroll
            for (int c=0;c<4;c++) br[c] = *(const uint4*)(Bg + c*8);
        }

        #pragma unroll
        for (int ks = 0; ks < 32; ks += 16){
            uint32_t af[4][4], bf[8][2];
            #pragma unroll
            for (int mf=0; mf<4; mf++){
                int row  = wm*64 + mf*16 + g;
                int base = row*PITCH + ks + t*2;
                af[mf][0] = *(const uint32_t*)&As[base];
                af[mf][1] = *(const uint32_t*)&As[base + 8*PITCH];
                af[mf][2] = *(const uint32_t*)&As[base + 8];
                af[mf][3] = *(const uint32_t*)&As[base + 8*PITCH + 8];
            }
            #pragma unroll
            for (int nf=0; nf<8; nf++){
                int coln = wn*64 + nf*8 + g;
                int base = coln*PITCH + ks + t*2;
                bf[nf][0] = *(const uint32_t*)&Bs[base];
                bf[nf][1] = *(const uint32_t*)&Bs[base + 8];
            }
            #pragma unroll
            for (int mf=0; mf<4; mf++)
                #pragma unroll
                for (int nf=0; nf<8; nf++)
                    mma_bf16(acc[mf][nf], af[mf], bf[nf]);
        }
        __syncthreads();
    }

    #pragma unroll
    for (int mf=0; mf<4; mf++){
        int r0 = m0 + wm*64 + mf*16 + g;
        #pragma unroll
        for (int nf=0; nf<8; nf++){
            int n = n0 + wn*64 + nf*8 + t*2;
            float2 bv = *(const float2*)(bias + n);
            float v00 = acc[mf][nf][0] + bv.x, v01 = acc[mf][nf][1] + bv.y;
            float v10 = acc[mf][nf][2] + bv.x, v11 = acc[mf][nf][3] + bv.y;
            if (EPI == 0){
                v00 = fmaxf(v00, 0.f); v01 = fmaxf(v01, 0.f);
                v10 = fmaxf(v10, 0.f); v11 = fmaxf(v11, 0.f);
            }
            __nv_bfloat162 h0 = __float22bfloat162_rn(make_float2(v00, v01));
            __nv_bfloat162 h1 = __float22bfloat162_rn(make_float2(v10, v11));
            *(__nv_bfloat162*)(Cb + (size_t)r0*N + n)     = h0;
            *(__nv_bfloat162*)(Cb + (size_t)(r0+8)*N + n) = h1;
            if (EPI == 1){
                *(float2*)(Cf + (size_t)r0*N + n)     = make_float2(v00, v01);
                *(float2*)(Cf + (size_t)(r0+8)*N + n) = make_float2(v10, v11);
            }
        }
    }
}

// ------------------------- bf16 logits GEMM (streamed sum-exp) ---------------
__global__ void __launch_bounds__(256) k_hgemm_logits(
        const __nv_bfloat16* __restrict__ A,   // [RT, FF]
        const __nv_bfloat16* __restrict__ B)   // [VV, FF]
{
    const int PITCH = 40;
    __shared__ __align__(16) __nv_bfloat16 As[128*PITCH];
    __shared__ __align__(16) __nv_bfloat16 Bs[256*PITCH];

    int tid  = threadIdx.x;
    int lane = tid & 31, wid = tid >> 5;
    int wm = wid >> 2, wn = wid & 3;
    int g  = lane >> 2, t = lane & 3;
    int m0 = blockIdx.y * 128;
    int n0 = blockIdx.x * 256;

    int a_r = tid >> 1;
    int a_c = (tid & 1) * 2;
    int b_r = tid;

    uint4 ar[2], br[4];
    {
        const __nv_bfloat16* Ag = A + (size_t)(m0 + a_r)*FF + a_c*8;
        const __nv_bfloat16* Bg = B + (size_t)(n0 + b_r)*FF;
        ar[0] = *(const uint4*)(Ag);
        ar[1] = *(const uint4*)(Ag + 8);
        #pragma unroll
        for (int c=0;c<4;c++) br[c] = *(const uint4*)(Bg + c*8);
    }

    float acc[4][8][4];
    #pragma unroll
    for (int i=0;i<4;i++)
        #pragma unroll
        for (int j=0;j<8;j++)
            #pragma unroll
            for (int q=0;q<4;q++) acc[i][j][q] = 0.f;

    for (int kt = 0; kt < FF; kt += 32){
        *(uint4*)&As[a_r*PITCH + a_c*8]     = ar[0];
        *(uint4*)&As[a_r*PITCH + a_c*8 + 8] = ar[1];
        #pragma unroll
        for (int c=0;c<4;c++) *(uint4*)&Bs[b_r*PITCH + c*8] = br[c];
        __syncthreads();

        if (kt + 32 < FF){
            const __nv_bfloat16* Ag = A + (size_t)(m0 + a_r)*FF + (kt+32) + a_c*8;
            const __nv_bfloat16* Bg = B + (size_t)(n0 + b_r)*FF + (kt+32);
            ar[0] = *(const uint4*)(Ag);
            ar[1] = *(const uint4*)(Ag + 8);
            #pragma unroll
            for (int c=0;c<4;c++) br[c] = *(const uint4*)(Bg + c*8);
        }

        #pragma unroll
        for (int ks = 0; ks < 32; ks += 16){
            uint32_t af[4][4], bf[8][2];
            #pragma unroll
            for (int mf=0; mf<4; mf++){
                int row  = wm*64 + mf*16 + g;
                int base = row*PITCH + ks + t*2;
                af[mf][0] = *(const uint32_t*)&As[base];
                af[mf][1] = *(const uint32_t*)&As[base + 8*PITCH];
                af[mf][2] = *(const uint32_t*)&As[base + 8];
                af[mf][3] = *(const uint32_t*)&As[base + 8*PITCH + 8];
            }
            #pragma unroll
            for (int nf=0; nf<8; nf++){
                int coln = wn*64 + nf*8 + g;
                int base = coln*PITCH + ks + t*2;
                bf[nf][0] = *(const uint32_t*)&Bs[base];
                bf[nf][1] = *(const uint32_t*)&Bs[base + 8];
            }
            #pragma unroll
            for (int mf=0; mf<4; mf++)
                #pragma unroll
                for (int nf=0; nf<8; nf++)
                    mma_bf16(acc[mf][nf], af[mf], bf[nf]);
        }
        __syncthreads();
    }

    #pragma unroll
    for (int mf=0; mf<4; mf++){
        float rlo = 0.f, rhi = 0.f;
        #pragma unroll
        for (int nf=0; nf<8; nf++){
            int nb = n0 + wn*64 + nf*8 + t*2;
            float e0 = __expf(acc[mf][nf][0]*INV_SQRT_F);
            float e1 = __expf(acc[mf][nf][1]*INV_SQRT_F);
            float e2 = __expf(acc[mf][nf][2]*INV_SQRT_F);
            float e3 = __expf(acc[mf][nf][3]*INV_SQRT_F);
            if (nb == 0){ e0 = 0.f; e2 = 0.f; }
            rlo += e0 + e1;
            rhi += e2 + e3;
        }
        rlo += __shfl_xor_sync(0xffffffffu, rlo, 1);
        rlo += __shfl_xor_sync(0xffffffffu, rlo, 2);
        rhi += __shfl_xor_sync(0xffffffffu, rhi, 1);
        rhi += __shfl_xor_sync(0xffffffffu, rhi, 2);
        if (t == 0){
            int row = m0 + wm*64 + mf*16 + g;
            atomicAdd(&g_se[row],     rlo);
            atomicAdd(&g_se[row + 8], rhi);
        }
    }
}

// ------------------------- target logit + sumexp init -----------------------
__global__ void __launch_bounds__(256) k_tgt(const void* __restrict__ tg, const float* __restrict__ emb){
    int tid = threadIdx.x, lane = tid & 31, w = tid >> 5;
    int r = blockIdx.x * 8 + w;
    int s = r >> 6, b = r & 63;
    int t = load_idx(tg, b*SS + s, g_tg64);
    float dot = 0.f;
    if (t != 0){
        const float4* o = (const float4*)(g_O + (size_t)r*FF);
        const float4* e = (const float4*)(emb + (size_t)t*FF);
        #pragma unroll
        for (int it = 0; it < 4; it++){
            float4 ov = o[lane + 32*it];
            float4 ev = e[lane + 32*it];
            dot += ov.x*ev.x + ov.y*ev.y + ov.z*ev.z + ov.w*ev.w;
        }
    }
    #pragma unroll
    for (int off = 16; off; off >>= 1) dot += __shfl_down_sync(0xffffffffu, dot, off);
    if (lane == 0){
        g_tl[r]   = dot * INV_SQRT_F;
        g_mask[r] = (t != 0) ? 1.f : 0.f;
        g_se[r]   = 1.f;
    }
}

// ------------------------- per-step loss + global mean -----------------------
__global__ void __launch_bounds__(64) k_loss(float* __restrict__ out){
    int s = blockIdx.x, b = threadIdx.x;
    int r = s*BB + b;
    float m   = g_mask[r];
    float nll = (logf(g_se[r]) - g_tl[r]) * m;
    float nn = nll, mm = m;
    #pragma unroll
    for (int off = 16; off; off >>= 1){
        nn += __shfl_down_sync(0xffffffffu, nn, off);
        mm += __shfl_down_sync(0xffffffffu, mm, off);
    }
    __shared__ float sn[2], sm[2];
    if ((b & 31) == 0){ sn[b>>5] = nn; sm[b>>5] = mm; }
    __syncthreads();
    if (b == 0){
        float N_ = sn[0] + sn[1], M_ = sm[0] + sm[1];
        atomicAdd(out, (N_ / fmaxf(M_, 1.f)) * (1.f/SS));
    }
}

// ------------------------- launch -------------------------------------------
extern "C" void kernel_launch(void* const* d_in, const int* in_sizes, int n_in,
                              void* d_out, int out_size){
    const void*  inp   = d_in[0];
    const void*  tgt   = d_in[1];
    const float* see   = (const float*)d_in[2];
    const float* bias  = (const float*)d_in[3];
    const float* W_in  = (const float*)d_in[4];
    const float* b_in  = (const float*)d_in[5];
    const float* W_out = (const float*)d_in[6];
    const float* b_out = (const float*)d_in[7];
    const float* ln_g  = (const float*)d_in[8];
    const float* ln_b  = (const float*)d_in[9];
    const float* emb   = (const float*)d_in[10];
    float* out = (float*)d_out;

    void *pV, *pP, *pO, *pOh, *pEh, *pYh, *pHh, *pWih, *pWoh;
    cudaGetSymbolAddress(&pV, g_V);
    cudaGetSymbolAddress(&pP, g_P);
    cudaGetSymbolAddress(&pO, g_O);
    cudaGetSymbolAddress(&pOh, g_Oh);
    cudaGetSymbolAddress(&pEh, g_embh);
    cudaGetSymbolAddress(&pYh, g_Yh);
    cudaGetSymbolAddress(&pHh, g_Hh);
    cudaGetSymbolAddress(&pWih, g_Winh);
    cudaGetSymbolAddress(&pWoh, g_Wouth);

    k_init<<<1, 256>>>((const int*)inp, (const int*)tgt, out);
    k_cvt_emb<<<(int)(((size_t)VV*FF)/1024), 256>>>(emb);
    k_cvt<<<(int)(((size_t)HH*FF)/1024), 256>>>(W_in,  (__nv_bfloat16*)pWih);
    k_cvt<<<(int)(((size_t)FF*HH)/1024), 256>>>(W_out, (__nv_bfloat16*)pWoh);
    k_gather<<<RT, 128>>>(inp, emb);

    // P = Vecs @ see_top + bias  (fp32: feeds the recurrence)
    k_gemm_nn<<<dim3(FF/128, RT/128), 256>>>((const float*)pV, see, bias, (float*)pP, RT, FF, FF);

    // persistent recurrence: all 256 steps in one launch
    k_recurr_all<<<64, 128>>>(see);

    k_ln<<<RT, 128>>>(ln_g, ln_b);    // -> g_Yh (bf16)

    // H = relu(Y @ W_in^T + b_in)   (bf16 out)
    k_hgemm<0><<<dim3(HH/256, RT/128), 256>>>(
        (const __nv_bfloat16*)pYh, (const __nv_bfloat16*)pWih, b_in,
        (__nv_bfloat16*)pHh, nullptr, HH, FF);
    // O = H @ W_out^T + b_out       (fp32 + bf16 out)
    k_hgemm<1><<<dim3(FF/256, RT/128), 256>>>(
        (const __nv_bfloat16*)pHh, (const __nv_bfloat16*)pWoh, b_out,
        (__nv_bfloat16*)pOh, (float*)pO, FF, HH);

    k_tgt<<<RT/8, 256>>>(tgt, emb);

    // logits + streamed sum-exp on tensor cores (no logits buffer)
    k_hgemm_logits<<<dim3(VV/256, RT/128), 256>>>(
        (const __nv_bfloat16*)pOh, (const __nv_bfloat16*)pEh);

    k_loss<<<SS, 64>>>(out);
}